// round 1
// baseline (speedup 1.0000x reference)
#include <cuda_runtime.h>

// Problem constants
#define BB 16
#define NN 128
#define HD 128
#define ED 64
#define MD 128

// Scratch: c1[b,j,m] = h[b,j]@W1 + bias ; c2[b,i,m] = h[b,i]@W2
__device__ float g_c1[BB * NN * MD];
__device__ float g_c2[BB * NN * MD];

// ---------------- packed fp32x2 helpers (sm_100+) ----------------
__device__ __forceinline__ unsigned long long pk2(float x, float y) {
    unsigned long long r;
    asm("mov.b64 %0, {%1, %2};" : "=l"(r) : "f"(x), "f"(y));
    return r;
}
__device__ __forceinline__ void upk2(unsigned long long v, float& x, float& y) {
    asm("mov.b64 {%0, %1}, %2;" : "=f"(x), "=f"(y) : "l"(v));
}
__device__ __forceinline__ unsigned long long fma2(unsigned long long a,
                                                   unsigned long long b,
                                                   unsigned long long c) {
    unsigned long long d;
    asm("fma.rn.f32x2 %0, %1, %2, %3;" : "=l"(d) : "l"(a), "l"(b), "l"(c));
    return d;
}

// ---------------- Kernel 1: precompute c1, c2 ----------------
// Grid: 128 blocks x 128 threads. Each block handles 16 rows of h (row = b*N+n).
// Thread t owns output column m = t; 16 accumulator pairs in registers.
__global__ __launch_bounds__(128) void precompute_kernel(
    const float* __restrict__ h, const float* __restrict__ W,
    const float* __restrict__ bias) {
    __shared__ float h_s[16 * 128];
    const int t = threadIdx.x;
    const int rb = blockIdx.x * 16;  // row base in [0, 2048)

#pragma unroll
    for (int q = 0; q < 16; q++)
        h_s[q * 128 + t] = h[(size_t)(rb + q) * HD + t];
    __syncthreads();

    float acc1[16], acc2[16];
#pragma unroll
    for (int r = 0; r < 16; r++) { acc1[r] = 0.f; acc2[r] = 0.f; }

#pragma unroll 4
    for (int k = 0; k < HD; k++) {
        const float w1 = W[(size_t)k * MD + t];            // W1 row k
        const float w2 = W[(size_t)(HD + k) * MD + t];     // W2 row k
#pragma unroll
        for (int r = 0; r < 16; r++) {
            const float hv = h_s[r * 128 + k];
            acc1[r] = fmaf(hv, w1, acc1[r]);
            acc2[r] = fmaf(hv, w2, acc2[r]);
        }
    }

    const float bv = bias[t];
#pragma unroll
    for (int r = 0; r < 16; r++) {
        g_c1[(size_t)(rb + r) * MD + t] = acc1[r] + bv;
        g_c2[(size_t)(rb + r) * MD + t] = acc2[r];
    }
}

// ---------------- Kernel 2: message construction ----------------
// Grid: B*N/2 = 1024 blocks x 128 threads.
// Block handles two (b,i) rows: group g = t/64 -> i = 2*ip + g.
// Thread p (0..63) in a group owns output columns {2p, 2p+1} (packed f32x2).
// W3 column-pair is preloaded into 64 packed registers.
// e row is staged in shared pre-duplicated as (v,v) pairs for broadcast fma2.
// adj==0 rows: pure zero store (no e read, no compute).
__global__ __launch_bounds__(128) void message_kernel(
    const float* __restrict__ e, const float* __restrict__ adj,
    const float* __restrict__ W, float* __restrict__ out) {
    __shared__ unsigned long long e2_s[2][64];
    __shared__ float adj_s[2][128];

    const int t = threadIdx.x;
    const int g = t >> 6;
    const int p = t & 63;
    const int b = blockIdx.x >> 6;    // 64 = N/2 block-pairs per batch
    const int ip = blockIdx.x & 63;
    const int i = ip * 2 + g;
    const int bi = b * NN + i;

    // Preload W3 column pair (rows 256..319 of W) into registers.
    unsigned long long w3r[64];
#pragma unroll
    for (int k = 0; k < ED; k++) {
        const float2 w = *reinterpret_cast<const float2*>(
            &W[(size_t)(2 * HD + k) * MD + 2 * p]);
        w3r[k] = pk2(w.x, w.y);
    }

    const float2 c2v =
        *reinterpret_cast<const float2*>(&g_c2[(size_t)bi * MD + 2 * p]);

    // adj row for this group's i
    adj_s[g][p]      = adj[(size_t)bi * NN + p];
    adj_s[g][p + 64] = adj[(size_t)bi * NN + p + 64];

    const float* __restrict__ erow = e + (size_t)bi * NN * ED;
    float* __restrict__ orow = out + (size_t)bi * NN * MD;

    for (int j = 0; j < NN; j++) {
        __syncthreads();  // previous iteration's e2_s reads done; adj_s visible
        const float a = adj_s[g][j];
        if (a != 0.0f) {
            const float v = erow[(size_t)j * ED + p];
            e2_s[g][p] = pk2(v, v);
        }
        __syncthreads();  // e2_s for this j visible to whole group

        if (a == 0.0f) {
            *reinterpret_cast<float2*>(&orow[(size_t)j * MD + 2 * p]) =
                make_float2(0.f, 0.f);
        } else {
            const float2 c1v = *reinterpret_cast<const float2*>(
                &g_c1[((size_t)b * NN + j) * MD + 2 * p]);
            unsigned long long acc = pk2(c1v.x + c2v.x, c1v.y + c2v.y);
#pragma unroll
            for (int k = 0; k < ED; k++)
                acc = fma2(e2_s[g][k], w3r[k], acc);
            float x, y;
            upk2(acc, x, y);
            *reinterpret_cast<float2*>(&orow[(size_t)j * MD + 2 * p]) =
                make_float2(x * a, y * a);
        }
    }
}

extern "C" void kernel_launch(void* const* d_in, const int* in_sizes, int n_in,
                              void* d_out, int out_size) {
    const float* h    = (const float*)d_in[0];
    const float* e    = (const float*)d_in[1];
    const float* adj  = (const float*)d_in[2];
    const float* W    = (const float*)d_in[3];
    const float* bias = (const float*)d_in[4];
    float* out = (float*)d_out;

    precompute_kernel<<<128, 128>>>(h, W, bias);
    message_kernel<<<BB * NN / 2, 128>>>(e, adj, W, out);
}

// round 2
// speedup vs baseline: 2.2276x; 2.2276x over previous
#include <cuda_runtime.h>

#define BB 16
#define NN 128
#define HD 128
#define ED 64
#define MD 128

typedef unsigned long long u64;

// Scratch: c1[b,j,m] = h[b,j]@W1 + bias ; c2[b,i,m] = h[b,i]@W2
__device__ float g_c1[BB * NN * MD];
__device__ float g_c2[BB * NN * MD];

// ---------------- packed fp32x2 helpers (sm_100+) ----------------
__device__ __forceinline__ u64 pk2(float x, float y) {
    u64 r;
    asm("mov.b64 %0, {%1, %2};" : "=l"(r) : "f"(x), "f"(y));
    return r;
}
__device__ __forceinline__ void upk2(u64 v, float& x, float& y) {
    asm("mov.b64 {%0, %1}, %2;" : "=f"(x), "=f"(y) : "l"(v));
}
__device__ __forceinline__ u64 fma2(u64 a, u64 b, u64 c) {
    u64 d;
    asm("fma.rn.f32x2 %0, %1, %2, %3;" : "=l"(d) : "l"(a), "l"(b), "l"(c));
    return d;
}

// ---------------- Kernel 1: precompute c1, c2 ----------------
// 256 blocks x 128 threads; each block handles 8 rows of h (row = b*N+n).
__global__ __launch_bounds__(128) void precompute_kernel(
    const float* __restrict__ h, const float* __restrict__ W,
    const float* __restrict__ bias) {
    __shared__ float h_s[8 * 128];
    const int t = threadIdx.x;
    const int rb = blockIdx.x * 8;  // row base in [0, 2048)

#pragma unroll
    for (int q = 0; q < 8; q++)
        h_s[q * 128 + t] = h[(size_t)(rb + q) * HD + t];
    __syncthreads();

    float acc1[8], acc2[8];
#pragma unroll
    for (int r = 0; r < 8; r++) { acc1[r] = 0.f; acc2[r] = 0.f; }

#pragma unroll 4
    for (int k = 0; k < HD; k++) {
        const float w1 = W[(size_t)k * MD + t];         // W1 row k
        const float w2 = W[(size_t)(HD + k) * MD + t];  // W2 row k
#pragma unroll
        for (int r = 0; r < 8; r++) {
            const float hv = h_s[r * 128 + k];
            acc1[r] = fmaf(hv, w1, acc1[r]);
            acc2[r] = fmaf(hv, w2, acc2[r]);
        }
    }

    const float bv = bias[t];
#pragma unroll
    for (int r = 0; r < 8; r++) {
        g_c1[(size_t)(rb + r) * MD + t] = acc1[r] + bv;
        g_c2[(size_t)(rb + r) * MD + t] = acc2[r];
    }
}

// ---------------- Kernel 2: message construction ----------------
// Grid: B*N = 2048 blocks, 256 threads = 8 warps, one (b,i) per block.
// Active-j compaction; rounds of 32 active j's.
// Warp-pair: jgrp = warp>>1 picks the j-octet, warp&1 picks the m-half.
// Each lane owns one m-pair p; e staged in shared as duplicated (v,v) u64.
// W3 pairs fetched per 8-k chunk via LDG.64 (L1-resident), reused over 8 j.
__global__ __launch_bounds__(256, 3) void message_kernel(
    const float* __restrict__ e, const float* __restrict__ adj,
    const float* __restrict__ W, float* __restrict__ out) {
    __shared__ u64 edup[32][ED];     // 16 KB: duplicated e pairs
    __shared__ float adjrow[NN];
    __shared__ int actlist[NN];
    __shared__ int nact_s;

    const int t = threadIdx.x;
    const int warp = t >> 5, lane = t & 31;
    const int bi = blockIdx.x;
    const int b = bi >> 7;

    if (t == 0) nact_s = 0;
    __syncthreads();
    if (t < NN) {
        const float a = __ldg(&adj[(size_t)bi * NN + t]);
        adjrow[t] = a;
        if (a != 0.0f) actlist[atomicAdd(&nact_s, 1)] = t;
    }
    __syncthreads();
    const int NA = nact_s;

    // Zero all inactive rows (coalesced streaming stores).
    {
        const float4 z = make_float4(0.f, 0.f, 0.f, 0.f);
#pragma unroll
        for (int it = 0; it < 16; it++) {
            const int idx = t + it * 256;          // 0..4095
            const int j = idx >> 5;                // 0..127
            const int q = (idx & 31) << 2;         // 0..124
            if (adjrow[j] == 0.0f)
                __stcs((float4*)&out[((size_t)bi * NN + j) * MD + q], z);
        }
    }

    const int p = ((warp & 1) << 5) + lane;  // m-pair index 0..63
    const int jgrp = warp >> 1;              // 0..3 -> j-octet within round
    const float2 c2v =
        *reinterpret_cast<const float2*>(&g_c2[(size_t)bi * MD + 2 * p]);
    const float* __restrict__ Wp = &W[(size_t)(2 * HD) * MD + 2 * p];

    for (int r0 = 0; r0 < NA; r0 += 32) {
        const int nr = min(32, NA - r0);

        // Stage e rows for active j's, duplicated as (v,v) pairs.
#pragma unroll
        for (int it = 0; it < 2; it++) {
            const int idx = t + it * 256;     // 0..511
            const int jl = idx >> 4;          // 0..31
            const int kc = (idx & 15) << 2;   // 0..60
            if (jl < nr) {
                const int jg = actlist[r0 + jl];
                const float4 ev = __ldcs(reinterpret_cast<const float4*>(
                    &e[((size_t)bi * NN + jg) * ED + kc]));
                ulonglong2* dst = reinterpret_cast<ulonglong2*>(&edup[jl][kc]);
                dst[0] = make_ulonglong2(pk2(ev.x, ev.x), pk2(ev.y, ev.y));
                dst[1] = make_ulonglong2(pk2(ev.z, ev.z), pk2(ev.w, ev.w));
            }
        }
        __syncthreads();

        const int jbase = jgrp * 8;
        int myn = nr - jbase;
        if (myn > 8) myn = 8;
        if (myn > 0) {
            u64 acc[8];
            int jglob[8];
#pragma unroll
            for (int jj = 0; jj < 8; jj++) {
                if (jj < myn) {
                    const int jg = actlist[r0 + jbase + jj];
                    jglob[jj] = jg;
                    const float2 c1v = *reinterpret_cast<const float2*>(
                        &g_c1[((size_t)b * NN + jg) * MD + 2 * p]);
                    acc[jj] = pk2(c1v.x + c2v.x, c1v.y + c2v.y);
                }
            }

#pragma unroll 2
            for (int kc = 0; kc < ED; kc += 8) {
                u64 w[8];
#pragma unroll
                for (int u = 0; u < 8; u++)
                    w[u] = *reinterpret_cast<const u64*>(
                        &Wp[(size_t)(kc + u) * MD]);
#pragma unroll
                for (int jj = 0; jj < 8; jj++) {
                    if (jj < myn) {
                        const ulonglong2* er =
                            reinterpret_cast<const ulonglong2*>(
                                &edup[jbase + jj][kc]);
                        const ulonglong2 e01 = er[0];
                        const ulonglong2 e23 = er[1];
                        const ulonglong2 e45 = er[2];
                        const ulonglong2 e67 = er[3];
                        u64 a = acc[jj];
                        a = fma2(e01.x, w[0], a);
                        a = fma2(e01.y, w[1], a);
                        a = fma2(e23.x, w[2], a);
                        a = fma2(e23.y, w[3], a);
                        a = fma2(e45.x, w[4], a);
                        a = fma2(e45.y, w[5], a);
                        a = fma2(e67.x, w[6], a);
                        a = fma2(e67.y, w[7], a);
                        acc[jj] = a;
                    }
                }
            }

#pragma unroll
            for (int jj = 0; jj < 8; jj++) {
                if (jj < myn) {
                    const float a = adjrow[jglob[jj]];
                    float x, y;
                    upk2(acc[jj], x, y);
                    __stcs(reinterpret_cast<float2*>(
                               &out[((size_t)bi * NN + jglob[jj]) * MD + 2 * p]),
                           make_float2(x * a, y * a));
                }
            }
        }
        __syncthreads();
    }
}

extern "C" void kernel_launch(void* const* d_in, const int* in_sizes, int n_in,
                              void* d_out, int out_size) {
    const float* h    = (const float*)d_in[0];
    const float* e    = (const float*)d_in[1];
    const float* adj  = (const float*)d_in[2];
    const float* W    = (const float*)d_in[3];
    const float* bias = (const float*)d_in[4];
    float* out = (float*)d_out;

    precompute_kernel<<<256, 128>>>(h, W, bias);
    message_kernel<<<BB * NN, 256>>>(e, adj, W, out);
}